// round 7
// baseline (speedup 1.0000x reference)
#include <cuda_runtime.h>
#include <math.h>
#include <stdint.h>

// Problem constants
constexpr int Bb = 2;
constexpr int Tt = 2048;
constexpr int Cc = 1024;
constexpr int Hh = 16;
constexpr int Dd = 64;
constexpr int Mrows = Bb * Tt;        // 4096
constexpr int C3 = 3 * Cc;            // 3072
constexpr int BH = Bb * Hh;           // 32
constexpr int NQT = Tt / 128;         // 16

// Device scratch (allocation-free rule: __device__ globals)
__device__ float g_qkv[(size_t)Mrows * C3];    // [4096, 3072]
__device__ float g_attnv[(size_t)Mrows * Cc];  // [4096, 1024]

// ---------------------------------------------------------------------------
// helpers
// ---------------------------------------------------------------------------
__device__ __forceinline__ uint32_t f2tf(float f) {
    uint32_t u;
    asm("cvt.rna.tf32.f32 %0, %1;" : "=r"(u) : "f"(f));
    return u;
}
__device__ __forceinline__ float ex2f(float x) {
    float y;
    asm("ex2.approx.ftz.f32 %0, %1;" : "=f"(y) : "f"(x));
    return y;
}
__device__ __forceinline__ void mma8(float* c, const uint32_t* a, const uint32_t* b) {
    asm volatile(
        "mma.sync.aligned.m16n8k8.row.col.f32.tf32.tf32.f32 "
        "{%0,%1,%2,%3},{%4,%5,%6,%7},{%8,%9},{%0,%1,%2,%3};"
        : "+f"(c[0]), "+f"(c[1]), "+f"(c[2]), "+f"(c[3])
        : "r"(a[0]), "r"(a[1]), "r"(a[2]), "r"(a[3]), "r"(b[0]), "r"(b[1]));
}
__device__ __forceinline__ void cpasync16(uint32_t saddr, const void* gptr) {
    asm volatile("cp.async.ca.shared.global [%0], [%1], 16;\n" ::"r"(saddr), "l"(gptr));
}

// ---------------------------------------------------------------------------
// Dense NN GEMM: C[M,N] = A[M,K] @ B[K,N] + bias[N]  (tf32, cp.async 3-stage)
// ---------------------------------------------------------------------------
__global__ __launch_bounds__(256, 2) void gemm_nn_tf32(
    const float* __restrict__ A, int lda,
    const float* __restrict__ Bm, int ldb,
    const float* __restrict__ bias,
    float* __restrict__ Cm, int ldc, int Kd)
{
    extern __shared__ float sh[];
    constexpr int STG_F = 128 * 20 + 16 * 128;

    const int tid = threadIdx.x;
    const int wid = tid >> 5, lane = tid & 31;
    const int g = lane >> 2, tg = lane & 3;
    const int warp_m = wid & 1, warp_n = wid >> 1;
    const int row0 = blockIdx.y * 128;
    const int col0 = blockIdx.x * 128;

    const uint32_t shbase = (uint32_t)__cvta_generic_to_shared(sh);

    auto issue = [&](int s, int k0) {
#pragma unroll
        for (int i = 0; i < 2; i++) {
            int c = tid + i * 256;
            int m = c >> 2, kq = (c & 3) * 4;
            cpasync16(shbase + (s * STG_F + m * 20 + kq) * 4,
                      A + (size_t)(row0 + m) * lda + k0 + kq);
        }
#pragma unroll
        for (int i = 0; i < 2; i++) {
            int c = tid + i * 256;
            int k = c >> 5, nq = (c & 31) * 4;
            int nx = nq ^ ((k & 3) << 3);
            cpasync16(shbase + (s * STG_F + 128 * 20 + k * 128 + nx) * 4,
                      Bm + (size_t)(k0 + k) * ldb + col0 + nq);
        }
        asm volatile("cp.async.commit_group;\n");
    };

    const int nIter = Kd / 16;
    issue(0, 0);
    issue(1, 16);

    float acc[4][4][4] = {};

    for (int j = 0; j < nIter; j++) {
        if (j == nIter - 1) {
            asm volatile("cp.async.wait_group 0;\n");
        } else {
            asm volatile("cp.async.wait_group 1;\n");
        }
        __syncthreads();
        const float* Asj = sh + (j % 3) * STG_F;
        const float* Bsj = Asj + 128 * 20;
#pragma unroll
        for (int ks = 0; ks < 16; ks += 8) {
            uint32_t af[4][4], bf[4][2];
#pragma unroll
            for (int mi = 0; mi < 4; mi++) {
                int m = warp_m * 64 + mi * 16;
                af[mi][0] = f2tf(Asj[(m + g) * 20 + ks + tg]);
                af[mi][1] = f2tf(Asj[(m + g + 8) * 20 + ks + tg]);
                af[mi][2] = f2tf(Asj[(m + g) * 20 + ks + tg + 4]);
                af[mi][3] = f2tf(Asj[(m + g + 8) * 20 + ks + tg + 4]);
            }
            const int xr = tg << 3;
#pragma unroll
            for (int ni = 0; ni < 4; ni++) {
                int n = warp_n * 32 + ni * 8;
                bf[ni][0] = f2tf(Bsj[(ks + tg) * 128 + ((n + g) ^ xr)]);
                bf[ni][1] = f2tf(Bsj[(ks + tg + 4) * 128 + ((n + g) ^ xr)]);
            }
#pragma unroll
            for (int mi = 0; mi < 4; mi++)
#pragma unroll
                for (int ni = 0; ni < 4; ni++) mma8(acc[mi][ni], af[mi], bf[ni]);
        }
        if (j + 2 < nIter) issue((j + 2) % 3, (j + 2) * 16);
    }

#pragma unroll
    for (int mi = 0; mi < 4; mi++) {
#pragma unroll
        for (int ni = 0; ni < 4; ni++) {
            int m = row0 + warp_m * 64 + mi * 16 + g;
            int n = col0 + warp_n * 32 + ni * 8 + tg * 2;
            float2 o0 = {acc[mi][ni][0] + bias[n], acc[mi][ni][1] + bias[n + 1]};
            float2 o1 = {acc[mi][ni][2] + bias[n], acc[mi][ni][3] + bias[n + 1]};
            *(float2*)(Cm + (size_t)m * ldc + n) = o0;
            *(float2*)(Cm + (size_t)(m + 8) * ldc + n) = o1;
        }
    }
}

// ---------------------------------------------------------------------------
// Fused attention: per (bh, q-tile of 128). Two passes over k-tiles (128).
// Pass A: S = Q.K^T (log2-domain, scale folded into Q), per-tile row stats.
// Combine in smem. Pass B: recompute S, P = 2^(s-mt)*f -> gmem attn_w + P@V.
// Pass B stages P through a 128x68 smem buffer in TWO 64-col halves
// (the full 128x128 tile does not fit -- this was the round-6 bug).
//
// Dynamic smem layout (floats):
//   Qs    [128*68]  tf32 (u32)           @ 0
//   Ks    [2][128*68] raw float          @ 8704
//   Vs    [2][128*64] raw float (xor-sw) @ 26112
//   Ps    [128*68] float (64-col half)   @ 42496
//   stm   [16*128] float                 @ 51200
//   stl   [16*128] float                 @ 53248
//   fct   [128*16] float                 @ 55296
//   total 57344 floats = 229376 B
// ---------------------------------------------------------------------------
__global__ __launch_bounds__(512, 1) void attn_fused(float* __restrict__ S)
{
    extern __shared__ float dyn[];
    uint32_t* Qs = (uint32_t*)dyn;              // tf32
    float* Ks  = dyn + 8704;                    // raw, 2 bufs of 8704
    float* Vs  = dyn + 26112;                   // raw, 2 bufs of 8192
    float* Ps  = dyn + 42496;
    float* stm = dyn + 51200;
    float* stl = dyn + 53248;
    float* fct = dyn + 55296;
    __shared__ float sred[128 * 4];

    const int qt = (NQT - 1) - blockIdx.x;      // heavy tiles first
    const int q0 = qt * 128;
    const int bh = blockIdx.y;
    const int b = bh / Hh, h = bh % Hh;
    const int tid = threadIdx.x;
    const int wid = tid >> 5, lane = tid & 31;
    const int g = lane >> 2, tg = lane & 3;
    const int wm = wid & 3, wn = wid >> 2;

    float* Sb = S + (size_t)bh * Tt * Tt;

    // ---- zero-fill the strictly-upper region of this block's rows ----
    {
        const int cz4 = blockIdx.x * 32;        // float4s per row to zero
        const float4 z = {0.f, 0.f, 0.f, 0.f};
        for (int i = tid; i < 128 * cz4; i += 512) {
            int r = i / cz4, c = (i % cz4) * 4;
            *(float4*)(Sb + (size_t)(q0 + r) * Tt + q0 + 128 + c) = z;
        }
    }

    // ---- load Q tile -> tf32, scale*log2(e) folded in ----
    const float QS = 0.125f * 1.44269504f;
    {
        const float* Qg = g_qkv + (size_t)(b * Tt + q0) * C3 + h * Dd;
        for (int i = tid; i < 128 * 16; i += 512) {
            int r = i >> 4, c4 = (i & 15) * 4;
            float4 v = *(const float4*)(Qg + (size_t)r * C3 + c4);
            Qs[r * 68 + c4 + 0] = f2tf(v.x * QS);
            Qs[r * 68 + c4 + 1] = f2tf(v.y * QS);
            Qs[r * 68 + c4 + 2] = f2tf(v.z * QS);
            Qs[r * 68 + c4 + 3] = f2tf(v.w * QS);
        }
    }

    const float* Kg = g_qkv + (size_t)(b * Tt) * C3 + Cc + h * Dd;
    const float* Vg = g_qkv + (size_t)(b * Tt) * C3 + 2 * Cc + h * Dd;
    const uint32_t shb = (uint32_t)__cvta_generic_to_shared(dyn);

    auto issueK = [&](int buf, int kt) {
#pragma unroll
        for (int i = 0; i < 4; i++) {
            int c = tid + i * 512;
            int r = c >> 4, c4 = (c & 15) * 4;
            cpasync16(shb + (8704 + buf * 8704 + r * 68 + c4) * 4,
                      Kg + (size_t)(kt * 128 + r) * C3 + c4);
        }
    };
    auto issueV = [&](int buf, int kt) {
#pragma unroll
        for (int i = 0; i < 4; i++) {
            int c = tid + i * 512;
            int r = c >> 4, c4 = (c & 15) * 4;
            int cx = c4 ^ ((r & 3) << 3);
            cpasync16(shb + (26112 + buf * 8192 + r * 64 + cx) * 4,
                      Vg + (size_t)(kt * 128 + r) * C3 + c4);
        }
    };

    const int nkt = qt + 1;
    const int nit = 2 * nkt;

    issueK(0, 0);
    asm volatile("cp.async.commit_group;\n");

    float acc_o[2][2][4] = {};

    for (int it = 0; it < nit; it++) {
        const int kt = (it < nkt) ? it : it - nkt;
        const bool pB = (it >= nkt);
        const int buf = it & 1;

        asm volatile("cp.async.wait_group 0;\n");
        __syncthreads();

        // prefetch next tiles (into the buffer the previous iter just freed)
        {
            int nx = it + 1;
            if (nx < nit) {
                int knx = (nx < nkt) ? nx : nx - nkt;
                issueK(nx & 1, knx);
                if (nx >= nkt) issueV(nx & 1, knx);
            }
            asm volatile("cp.async.commit_group;\n");
        }

        // ---- S mma: 128x128, warp tile 32x32 ----
        const float* Kb = Ks + buf * 8704;
        float acc[2][4][4] = {};
#pragma unroll
        for (int ks = 0; ks < 64; ks += 8) {
            uint32_t af[2][4], bf[4][2];
#pragma unroll
            for (int mi = 0; mi < 2; mi++) {
                int m = wm * 32 + mi * 16;
                af[mi][0] = Qs[(m + g) * 68 + ks + tg];
                af[mi][1] = Qs[(m + g + 8) * 68 + ks + tg];
                af[mi][2] = Qs[(m + g) * 68 + ks + tg + 4];
                af[mi][3] = Qs[(m + g + 8) * 68 + ks + tg + 4];
            }
#pragma unroll
            for (int ni = 0; ni < 4; ni++) {
                int n = wn * 32 + ni * 8;
                bf[ni][0] = f2tf(Kb[(n + g) * 68 + ks + tg]);
                bf[ni][1] = f2tf(Kb[(n + g) * 68 + ks + tg + 4]);
            }
#pragma unroll
            for (int mi = 0; mi < 2; mi++)
#pragma unroll
                for (int ni = 0; ni < 4; ni++) mma8(acc[mi][ni], af[mi], bf[ni]);
        }

        // diagonal mask (tile-local col > row)
        if (kt == qt) {
#pragma unroll
            for (int mi = 0; mi < 2; mi++) {
                int r0 = wm * 32 + mi * 16 + g;
#pragma unroll
                for (int ni = 0; ni < 4; ni++) {
                    int c0 = wn * 32 + ni * 8 + tg * 2;
                    float* a = acc[mi][ni];
                    if (c0 > r0)         a[0] = -1e30f;
                    if (c0 + 1 > r0)     a[1] = -1e30f;
                    if (c0 > r0 + 8)     a[2] = -1e30f;
                    if (c0 + 1 > r0 + 8) a[3] = -1e30f;
                }
            }
        }

        if (!pB) {
            // ---- pass A: per-tile row stats (log2 domain) ----
            float mx[2][2];
#pragma unroll
            for (int mi = 0; mi < 2; mi++) {
                float m0 = -1e30f, m1 = -1e30f;
#pragma unroll
                for (int ni = 0; ni < 4; ni++) {
                    m0 = fmaxf(m0, fmaxf(acc[mi][ni][0], acc[mi][ni][1]));
                    m1 = fmaxf(m1, fmaxf(acc[mi][ni][2], acc[mi][ni][3]));
                }
                m0 = fmaxf(m0, __shfl_xor_sync(0xffffffffu, m0, 1));
                m0 = fmaxf(m0, __shfl_xor_sync(0xffffffffu, m0, 2));
                m1 = fmaxf(m1, __shfl_xor_sync(0xffffffffu, m1, 1));
                m1 = fmaxf(m1, __shfl_xor_sync(0xffffffffu, m1, 2));
                mx[mi][0] = m0; mx[mi][1] = m1;
            }
            if (tg == 0) {
#pragma unroll
                for (int mi = 0; mi < 2; mi++) {
                    sred[(wm * 32 + mi * 16 + g) * 4 + wn] = mx[mi][0];
                    sred[(wm * 32 + mi * 16 + g + 8) * 4 + wn] = mx[mi][1];
                }
            }
            __syncthreads();
            if (tid < 128) {
                stm[kt * 128 + tid] = fmaxf(fmaxf(sred[tid * 4], sred[tid * 4 + 1]),
                                            fmaxf(sred[tid * 4 + 2], sred[tid * 4 + 3]));
            }
            __syncthreads();
#pragma unroll
            for (int mi = 0; mi < 2; mi++) {
                float mt0 = stm[kt * 128 + wm * 32 + mi * 16 + g];
                float mt1 = stm[kt * 128 + wm * 32 + mi * 16 + g + 8];
                float s0 = 0.f, s1 = 0.f;
#pragma unroll
                for (int ni = 0; ni < 4; ni++) {
                    s0 += ex2f(acc[mi][ni][0] - mt0) + ex2f(acc[mi][ni][1] - mt0);
                    s1 += ex2f(acc[mi][ni][2] - mt1) + ex2f(acc[mi][ni][3] - mt1);
                }
                s0 += __shfl_xor_sync(0xffffffffu, s0, 1);
                s0 += __shfl_xor_sync(0xffffffffu, s0, 2);
                s1 += __shfl_xor_sync(0xffffffffu, s1, 1);
                s1 += __shfl_xor_sync(0xffffffffu, s1, 2);
                mx[mi][0] = s0; mx[mi][1] = s1;
            }
            __syncthreads();
            if (tg == 0) {
#pragma unroll
                for (int mi = 0; mi < 2; mi++) {
                    sred[(wm * 32 + mi * 16 + g) * 4 + wn] = mx[mi][0];
                    sred[(wm * 32 + mi * 16 + g + 8) * 4 + wn] = mx[mi][1];
                }
            }
            __syncthreads();
            if (tid < 128) {
                stl[kt * 128 + tid] = sred[tid * 4] + sred[tid * 4 + 1] +
                                      sred[tid * 4 + 2] + sred[tid * 4 + 3];
            }
            // ---- combine after last pass-A tile (per-thread-owned rows) ----
            if (it == nkt - 1 && tid < 128) {
                float m = -1e30f;
                for (int k2 = 0; k2 < nkt; k2++) m = fmaxf(m, stm[k2 * 128 + tid]);
                float l = 0.f;
                for (int k2 = 0; k2 < nkt; k2++)
                    l += stl[k2 * 128 + tid] * ex2f(stm[k2 * 128 + tid] - m);
                float inv = 1.0f / l;
                for (int k2 = 0; k2 < nkt; k2++)
                    fct[tid * 16 + k2] = ex2f(stm[k2 * 128 + tid] - m) * inv;
            }
        } else {
            // ---- pass B: two 64-col halves through the 128x68 Ps buffer ----
            const float* Vb = Vs + buf * 8192;
#pragma unroll
            for (int half = 0; half < 2; half++) {
                // warps owning this half's S columns stage P into Ps
                if ((wn >> 1) == half) {
                    const int nbase = (wn & 1) * 32;     // col within half
#pragma unroll
                    for (int mi = 0; mi < 2; mi++) {
                        int r0 = wm * 32 + mi * 16 + g;
                        int r1 = r0 + 8;
                        float mt0 = stm[kt * 128 + r0], f0 = fct[r0 * 16 + kt];
                        float mt1 = stm[kt * 128 + r1], f1 = fct[r1 * 16 + kt];
#pragma unroll
                        for (int ni = 0; ni < 4; ni++) {
                            int c0 = nbase + ni * 8 + tg * 2;   // 0..63
                            float* a = acc[mi][ni];
                            float2 p0 = {ex2f(a[0] - mt0) * f0, ex2f(a[1] - mt0) * f0};
                            float2 p1 = {ex2f(a[2] - mt1) * f1, ex2f(a[3] - mt1) * f1};
                            *(float2*)(Ps + r0 * 68 + c0) = p0;
                            *(float2*)(Ps + r1 * 68 + c0) = p1;
                        }
                    }
                }
                __syncthreads();

                // PV mma for this half: k in [half*64, half*64+64)
#pragma unroll
                for (int ks = 0; ks < 64; ks += 8) {
                    uint32_t af[2][4], bf[2][2];
#pragma unroll
                    for (int mi = 0; mi < 2; mi++) {
                        int m = wm * 32 + mi * 16;
                        af[mi][0] = f2tf(Ps[(m + g) * 68 + ks + tg]);
                        af[mi][1] = f2tf(Ps[(m + g + 8) * 68 + ks + tg]);
                        af[mi][2] = f2tf(Ps[(m + g) * 68 + ks + tg + 4]);
                        af[mi][3] = f2tf(Ps[(m + g + 8) * 68 + ks + tg + 4]);
                    }
                    const int xr = tg << 3;
                    const int vk = half * 64 + ks;
#pragma unroll
                    for (int ni = 0; ni < 2; ni++) {
                        int n = wn * 16 + ni * 8;
                        bf[ni][0] = f2tf(Vb[(vk + tg) * 64 + ((n + g) ^ xr)]);
                        bf[ni][1] = f2tf(Vb[(vk + tg + 4) * 64 + ((n + g) ^ xr)]);
                    }
#pragma unroll
                    for (int mi = 0; mi < 2; mi++)
#pragma unroll
                        for (int ni = 0; ni < 2; ni++) mma8(acc_o[mi][ni], af[mi], bf[ni]);
                }

                // write this half of P to gmem (final attn_w)
                {
                    int r = tid >> 2, cb = (tid & 3) * 16;
                    float* dst = Sb + (size_t)(q0 + r) * Tt + kt * 128 + half * 64 + cb;
                    const float* src = Ps + r * 68 + cb;
#pragma unroll
                    for (int j2 = 0; j2 < 4; j2++)
                        *(float4*)(dst + j2 * 4) = *(const float4*)(src + j2 * 4);
                }
                __syncthreads();   // protect Ps before next half / iteration
            }
        }
    }

    // ---- O epilogue ----
#pragma unroll
    for (int mi = 0; mi < 2; mi++) {
#pragma unroll
        for (int ni = 0; ni < 2; ni++) {
            int q = q0 + wm * 32 + mi * 16 + g;
            int n = wn * 16 + ni * 8 + tg * 2;
            float* d0 = g_attnv + (size_t)(b * Tt + q) * Cc + h * Dd + n;
            float* d1 = g_attnv + (size_t)(b * Tt + q + 8) * Cc + h * Dd + n;
            *(float2*)d0 = {acc_o[mi][ni][0], acc_o[mi][ni][1]};
            *(float2*)d1 = {acc_o[mi][ni][2], acc_o[mi][ni][3]};
        }
    }
}

// ---------------------------------------------------------------------------
extern "C" void kernel_launch(void* const* d_in, const int* in_sizes, int n_in,
                              void* d_out, int out_size)
{
    const float* x     = (const float*)d_in[0];
    const float* w_qkv = (const float*)d_in[1];
    const float* b_qkv = (const float*)d_in[2];
    const float* w_o   = (const float*)d_in[3];
    const float* b_o   = (const float*)d_in[4];

    float* out   = (float*)d_out;
    float* attnw = out + (size_t)Mrows * Cc;   // [o | attn_w]

    float* qkv_ptr   = nullptr;
    float* attnv_ptr = nullptr;
    cudaGetSymbolAddress((void**)&qkv_ptr,   g_qkv);
    cudaGetSymbolAddress((void**)&attnv_ptr, g_attnv);

    const int gemm_smem = 3 * (128 * 20 + 16 * 128) * 4;   // 55296
    const int attn_smem = 57344 * 4;                       // 229376
    static bool attr_set = false;
    if (!attr_set) {
        cudaFuncSetAttribute(gemm_nn_tf32, cudaFuncAttributeMaxDynamicSharedMemorySize,
                             gemm_smem);
        cudaFuncSetAttribute(attn_fused, cudaFuncAttributeMaxDynamicSharedMemorySize,
                             attn_smem);
        attr_set = true;
    }

    // 1) QKV projection
    {
        dim3 grid(C3 / 128, Mrows / 128);
        gemm_nn_tf32<<<grid, 256, gemm_smem>>>(x, Cc, w_qkv, C3, b_qkv, qkv_ptr, C3, Cc);
    }
    // 2) Fused attention (scores + softmax + PV + attn_w writeback)
    {
        dim3 grid(NQT, BH);
        attn_fused<<<grid, 512, attn_smem>>>(attnw);
    }
    // 3) Output projection
    {
        dim3 grid(Cc / 128, Mrows / 128);
        gemm_nn_tf32<<<grid, 256, gemm_smem>>>(attnv_ptr, Cc, w_o, Cc, b_o, out, Cc, Cc);
    }
}